// round 10
// baseline (speedup 1.0000x reference)
#include <cuda_runtime.h>
#include <cuda_fp16.h>
#include <math.h>
#include <stdint.h>

// ---------------- problem constants ----------------
#define DK   4096
#define EE   64
#define TOPK 8
#define BM   128
#define BN   128
#define CHUNK 32                  // K floats per stage
#define NSTAGE 128
#define NTHREADS 640              // 16 consumer warps + 4 producer warps
#define NCONS 512

// ---------------- smem layout (bytes) ----------------
#define A_STAGE 16384             // [k16(2)][plane(2)][128 rows][32B]
#define B_STAGE 16384             // [k16][pass][n16][lane] uint4
#define OFF_A 0
#define OFF_B (2*A_STAGE)                  // 32768
#define OFF_SIMS 0                         // overlay dead A+B after the loop
#define LDS_ 132
#define OFF_INVH (OFF_B + 4*B_STAGE)       // 98304
#define OFF_INVP (OFF_INVH + 512)          // 98816
#define SMEM_TOTAL (OFF_INVP + 512)        // 99328

__device__ float g_inv_pnorm[BN];
// B fragments: [kt(128)][k16(2)][pass(2)][n16(8)][lane(32)] -> uint4
__device__ uint4 g_bfrag[NSTAGE * 2 * 2 * 8 * 32];

// ---------------- helpers ----------------
__device__ __forceinline__ uint32_t smem_u32(const void* p) {
    uint32_t a;
    asm("{ .reg .u64 t; cvta.to.shared.u64 t, %1; cvt.u32.u64 %0, t; }" : "=r"(a) : "l"(p));
    return a;
}
__device__ __forceinline__ void ldm4(uint32_t* r, uint32_t addr) {
    asm volatile("ldmatrix.sync.aligned.m8n8.x4.shared.b16 {%0,%1,%2,%3}, [%4];"
        : "=r"(r[0]), "=r"(r[1]), "=r"(r[2]), "=r"(r[3]) : "r"(addr));
}
__device__ __forceinline__ uint4 lds128(uint32_t addr) {
    uint4 v;
    asm volatile("ld.shared.v4.u32 {%0,%1,%2,%3}, [%4];"
        : "=r"(v.x), "=r"(v.y), "=r"(v.z), "=r"(v.w) : "r"(addr));
    return v;
}
__device__ __forceinline__ void mma16816(float* c, const uint32_t* a, uint32_t b0, uint32_t b1) {
    asm volatile("mma.sync.aligned.m16n8k16.row.col.f32.f16.f16.f32 "
        "{%0,%1,%2,%3}, {%4,%5,%6,%7}, {%8,%9}, {%0,%1,%2,%3};"
        : "+f"(c[0]), "+f"(c[1]), "+f"(c[2]), "+f"(c[3])
        : "r"(a[0]), "r"(a[1]), "r"(a[2]), "r"(a[3]), "r"(b0), "r"(b1));
}
__device__ __forceinline__ void split2(float x, float y, uint32_t& uh, uint32_t& ul) {
    asm("cvt.rn.f16x2.f32 %0, %1, %2;" : "=r"(uh) : "f"(y), "f"(x));
    float lx = __half2float(__ushort_as_half((unsigned short)(uh & 0xffffu)));
    float ly = __half2float(__ushort_as_half((unsigned short)(uh >> 16)));
    float rx = x - lx, ry = y - ly;
    asm("cvt.rn.f16x2.f32 %0, %1, %2;" : "=r"(ul) : "f"(ry), "f"(rx));
}
#define CP_ASYNC16(dst, src) \
    asm volatile("cp.async.cg.shared.global [%0], [%1], 16;" :: "r"(dst), "l"(src))
#define CP_COMMIT() asm volatile("cp.async.commit_group;" ::: "memory")
#define CP_WAIT1()  asm volatile("cp.async.wait_group 1;"  ::: "memory")

// ---------------------------------------------------------------------------
// Kernel 1: fused prep — blocks [0,512): B split; blocks [512,640): proto norms
// ---------------------------------------------------------------------------
__global__ void prep_kernel(const float* __restrict__ proto) {
    if (blockIdx.x < 512) {
        int idx  = blockIdx.x * 256 + threadIdx.x;     // 131072 uint4
        int lane = idx & 31;
        int n16  = (idx >> 5) & 7;
        int pass = (idx >> 8) & 1;
        int k16  = (idx >> 9) & 1;
        int kt   = idx >> 10;
        int kt16 = kt * 2 + k16;
        uint32_t w[4];
#pragma unroll
        for (int r = 0; r < 4; r++) {
            int n  = n16 * 16 + ((r & 2) << 2) + (lane >> 2);
            int k0 = kt16 * 16 + (r & 1) * 8 + 2 * (lane & 3);
            float x = proto[(size_t)n * DK + k0];
            float y = proto[(size_t)n * DK + k0 + 1];
            uint32_t uh, ul;
            split2(x, y, uh, ul);
            w[r] = pass ? ul : uh;
        }
        g_bfrag[idx] = make_uint4(w[0], w[1], w[2], w[3]);
    } else {
        int row = blockIdx.x - 512;
        const float4* p = reinterpret_cast<const float4*>(proto + (size_t)row * DK);
        float s = 0.f;
        for (int i = threadIdx.x; i < DK / 4; i += blockDim.x) {
            float4 v = p[i];
            s += v.x * v.x + v.y * v.y + v.z * v.z + v.w * v.w;
        }
        for (int o = 16; o; o >>= 1) s += __shfl_down_sync(0xffffffffu, s, o);
        __shared__ float sm[8];
        if ((threadIdx.x & 31) == 0) sm[threadIdx.x >> 5] = s;
        __syncthreads();
        if (threadIdx.x == 0) {
            float t = 0.f;
            for (int i = 0; i < (int)(blockDim.x >> 5); i++) t += sm[i];
            g_inv_pnorm[row] = 1.0f / (sqrtf(t) + 1e-6f);
        }
    }
}

// ---------------------------------------------------------------------------
// Kernel 2: warp-specialized 3-pass split-fp16 mma GEMM + router epilogue
//   warps 0..15: pure MMA consumers (32x32 tiles)
//   warps 16..19: producers (A LDG/convert/STS, B cp.async, token norms)
// ---------------------------------------------------------------------------
extern "C" __global__ void __launch_bounds__(NTHREADS, 1)
router_mma(const float* __restrict__ h, float* __restrict__ out, int T) {
    extern __shared__ char smem[];
    const uint32_t smem_u = smem_u32(smem);
    const int tid  = threadIdx.x;
    const int wid  = tid >> 5;
    const int lane = tid & 31;
    const int t0   = blockIdx.x * BM;

    if (tid < BN) ((float*)(smem + OFF_INVP))[tid] = g_inv_pnorm[tid];

    // ---------------- consumer setup ----------------
    const int warp_m  = (wid >> 2) * 32;          // valid for wid<16
    const int warp_n4 = (wid & 3) * 2;
    const uint32_t bwoff = (uint32_t)warp_n4 * 512u + (uint32_t)lane * 16u;
    uint32_t aoff[2];
#pragma unroll
    for (int mi = 0; mi < 2; mi++) {
        int ar = warp_m + mi * 16 + ((lane >> 3) & 1) * 8 + (lane & 7);
        int kh = lane >> 4;
        aoff[mi] = (uint32_t)ar * 32u + (uint32_t)((kh ^ ((ar >> 2) & 1)) * 16);
    }
    float acc[2][4][4];
#pragma unroll
    for (int a = 0; a < 2; a++)
#pragma unroll
        for (int b = 0; b < 4; b++)
#pragma unroll
            for (int c = 0; c < 4; c++) acc[a][b][c] = 0.f;
    uint4 bh0, bh1, bl0, bl1;

    // ---------------- producer setup ----------------
    const int ptid = tid - NCONS;                 // 0..127 for producers
    const float* ag = h + (size_t)(t0 + (ptid & 127)) * DK;
    const char* bgp = (const char*)g_bfrag;
    float hsum = 0.f;
    float4 av[8];

    // ---- prologue ----
    if (wid >= 16) {
        // B stages 0,1,2 via cp.async (depth-3 so consumers may preload early)
#pragma unroll
        for (int s = 0; s < 3; s++) {
            uint32_t d = smem_u + OFF_B + (uint32_t)s * B_STAGE + (uint32_t)ptid * 128u;
            const char* g = bgp + (size_t)s * B_STAGE + (size_t)ptid * 128;
#pragma unroll
            for (int j = 0; j < 8; j++) CP_ASYNC16(d + j * 16, g + j * 16);
            CP_COMMIT();
        }
        // A chunk 0: load, convert -> buffer 0
#pragma unroll
        for (int j = 0; j < 8; j++) av[j] = ((const float4*)ag)[j];
#pragma unroll
        for (int k16q = 0; k16q < 2; k16q++)
#pragma unroll
            for (int halfq = 0; halfq < 2; halfq++) {
                float4 a0 = av[k16q * 4 + halfq * 2];
                float4 a1 = av[k16q * 4 + halfq * 2 + 1];
                uint32_t uh[4], ul[4];
                split2(a0.x, a0.y, uh[0], ul[0]); split2(a0.z, a0.w, uh[1], ul[1]);
                split2(a1.x, a1.y, uh[2], ul[2]); split2(a1.z, a1.w, uh[3], ul[3]);
                hsum += a0.x*a0.x + a0.y*a0.y + a0.z*a0.z + a0.w*a0.w
                      + a1.x*a1.x + a1.y*a1.y + a1.z*a1.z + a1.w*a1.w;
                uint32_t st = (uint32_t)k16q * 8192u + (uint32_t)ptid * 32u
                            + (uint32_t)((halfq ^ ((ptid >> 2) & 1)) * 16);
                *(uint4*)(smem + st)         = make_uint4(uh[0], uh[1], uh[2], uh[3]);
                *(uint4*)(smem + st + 4096u) = make_uint4(ul[0], ul[1], ul[2], ul[3]);
            }
        // A chunk 1 -> regs
#pragma unroll
        for (int j = 0; j < 8; j++) av[j] = ((const float4*)(ag + CHUNK))[j];
        CP_WAIT1();   // B0, B1 complete
    }
    __syncthreads();

    if (wid < 16) {   // preload stage-0 k16=0 B fragments
        uint32_t bb = smem_u + OFF_B;
        bh0 = lds128(bb + bwoff);        bh1 = lds128(bb + bwoff + 512);
        bl0 = lds128(bb + bwoff + 4096); bl1 = lds128(bb + bwoff + 4096 + 512);
    }

    // ---- main loop: one sync per 32-K stage ----
#pragma unroll 1
    for (int kt = 0; kt < NSTAGE; ++kt) {
        if (wid < 16) {
            // ---------------- consumer: pure MMA stream ----------------
            const uint32_t abase = smem_u + (uint32_t)(kt & 1) * A_STAGE;
            const uint32_t bbase = smem_u + OFF_B + (uint32_t)(kt & 3) * B_STAGE;
            uint32_t Ah[2][4], Al[2][4];
            ldm4(Ah[0], abase + aoff[0]);
            ldm4(Ah[1], abase + aoff[1]);
            ldm4(Al[0], abase + 4096u + aoff[0]);
            ldm4(Al[1], abase + 4096u + aoff[1]);
#pragma unroll
            for (int mi = 0; mi < 2; mi++) {
                mma16816(acc[mi][0], Ah[mi], bh0.x, bh0.y);
                mma16816(acc[mi][1], Ah[mi], bh0.z, bh0.w);
                mma16816(acc[mi][2], Ah[mi], bh1.x, bh1.y);
                mma16816(acc[mi][3], Ah[mi], bh1.z, bh1.w);
            }
#pragma unroll
            for (int mi = 0; mi < 2; mi++) {
                mma16816(acc[mi][0], Ah[mi], bl0.x, bl0.y);
                mma16816(acc[mi][1], Ah[mi], bl0.z, bl0.w);
                mma16816(acc[mi][2], Ah[mi], bl1.x, bl1.y);
                mma16816(acc[mi][3], Ah[mi], bl1.z, bl1.w);
            }
#pragma unroll
            for (int mi = 0; mi < 2; mi++) {
                mma16816(acc[mi][0], Al[mi], bh0.x, bh0.y);
                mma16816(acc[mi][1], Al[mi], bh0.z, bh0.w);
                mma16816(acc[mi][2], Al[mi], bh1.x, bh1.y);
                mma16816(acc[mi][3], Al[mi], bh1.z, bh1.w);
            }
            // k16 = 1
            ldm4(Ah[0], abase + 8192u + aoff[0]);
            ldm4(Ah[1], abase + 8192u + aoff[1]);
            ldm4(Al[0], abase + 8192u + 4096u + aoff[0]);
            ldm4(Al[1], abase + 8192u + 4096u + aoff[1]);
            bh0 = lds128(bbase + 8192u + bwoff);
            bh1 = lds128(bbase + 8192u + bwoff + 512);
            bl0 = lds128(bbase + 8192u + bwoff + 4096);
            bl1 = lds128(bbase + 8192u + bwoff + 4096 + 512);
#pragma unroll
            for (int mi = 0; mi < 2; mi++) {
                mma16816(acc[mi][0], Ah[mi], bh0.x, bh0.y);
                mma16816(acc[mi][1], Ah[mi], bh0.z, bh0.w);
                mma16816(acc[mi][2], Ah[mi], bh1.x, bh1.y);
                mma16816(acc[mi][3], Ah[mi], bh1.z, bh1.w);
            }
#pragma unroll
            for (int mi = 0; mi < 2; mi++) {
                mma16816(acc[mi][0], Ah[mi], bl0.x, bl0.y);
                mma16816(acc[mi][1], Ah[mi], bl0.z, bl0.w);
                mma16816(acc[mi][2], Ah[mi], bl1.x, bl1.y);
                mma16816(acc[mi][3], Ah[mi], bl1.z, bl1.w);
            }
#pragma unroll
            for (int mi = 0; mi < 2; mi++) {
                mma16816(acc[mi][0], Al[mi], bh0.x, bh0.y);
                mma16816(acc[mi][1], Al[mi], bh0.z, bh0.w);
                mma16816(acc[mi][2], Al[mi], bh1.x, bh1.y);
                mma16816(acc[mi][3], Al[mi], bh1.z, bh1.w);
            }
            // preload next stage k16=0 (slot kt+1 complete: producer depth-3)
            {
                uint32_t nb = smem_u + OFF_B + (uint32_t)((kt + 1) & 3) * B_STAGE;
                bh0 = lds128(nb + bwoff);        bh1 = lds128(nb + bwoff + 512);
                bl0 = lds128(nb + bwoff + 4096); bl1 = lds128(nb + bwoff + 4096 + 512);
            }
        } else {
            // ---------------- producer ----------------
            if (kt + 1 < NSTAGE) {   // convert chunk kt+1 -> other A buffer
                char* stg = smem + ((kt + 1) & 1) * A_STAGE;
#pragma unroll
                for (int k16q = 0; k16q < 2; k16q++)
#pragma unroll
                    for (int halfq = 0; halfq < 2; halfq++) {
                        float4 a0 = av[k16q * 4 + halfq * 2];
                        float4 a1 = av[k16q * 4 + halfq * 2 + 1];
                        uint32_t uh[4], ul[4];
                        split2(a0.x, a0.y, uh[0], ul[0]); split2(a0.z, a0.w, uh[1], ul[1]);
                        split2(a1.x, a1.y, uh[2], ul[2]); split2(a1.z, a1.w, uh[3], ul[3]);
                        hsum += a0.x*a0.x + a0.y*a0.y + a0.z*a0.z + a0.w*a0.w
                              + a1.x*a1.x + a1.y*a1.y + a1.z*a1.z + a1.w*a1.w;
                        uint32_t st = (uint32_t)k16q * 8192u + (uint32_t)ptid * 32u
                                    + (uint32_t)((halfq ^ ((ptid >> 2) & 1)) * 16);
                        *(uint4*)(stg + st)         = make_uint4(uh[0], uh[1], uh[2], uh[3]);
                        *(uint4*)(stg + st + 4096u) = make_uint4(ul[0], ul[1], ul[2], ul[3]);
                    }
            }
            {   // prefetch A chunk kt+2
                int ka = (kt + 2 < NSTAGE) ? kt + 2 : NSTAGE - 1;
                const float* a2 = ag + (size_t)ka * CHUNK;
#pragma unroll
                for (int j = 0; j < 8; j++) av[j] = ((const float4*)a2)[j];
            }
            {   // issue B(kt+3); keep wait depth so B(kt+2) done at barrier
                int ks = kt + 3;
                if (ks < NSTAGE) {
                    uint32_t d = smem_u + OFF_B + (uint32_t)(ks & 3) * B_STAGE
                               + (uint32_t)ptid * 128u;
                    const char* g = bgp + (size_t)ks * B_STAGE + (size_t)ptid * 128;
#pragma unroll
                    for (int j = 0; j < 8; j++) CP_ASYNC16(d + j * 16, g + j * 16);
                }
                CP_COMMIT();
                CP_WAIT1();
            }
        }
        __syncthreads();
    }

    // ---- token norms (producers own full rows) ----
    if (wid >= 16) ((float*)(smem + OFF_INVH))[ptid] = 1.0f / (sqrtf(hsum) + 1e-6f);
    __syncthreads();

    // ---- accumulators -> scaled cosine sims (overlay dead A+B) ----
    if (wid < 16) {
        const float* invh = (const float*)(smem + OFF_INVH);
        const float* invp = (const float*)(smem + OFF_INVP);
        float* sims = (float*)(smem + OFF_SIMS);
        const int warp_n = (wid & 3) * 32;
        int lr = lane >> 2, lc = (lane & 3) * 2;
#pragma unroll
        for (int mi = 0; mi < 2; mi++) {
            int row = warp_m + mi * 16 + lr;
            float ih0 = invh[row], ih1 = invh[row + 8];
#pragma unroll
            for (int nf = 0; nf < 4; nf++) {
                int col = warp_n + nf * 8 + lc;
                float ip0 = invp[col], ip1 = invp[col + 1];
                sims[row * LDS_ + col]           = acc[mi][nf][0] * ih0 * ip0;
                sims[row * LDS_ + col + 1]       = acc[mi][nf][1] * ih0 * ip1;
                sims[(row + 8) * LDS_ + col]     = acc[mi][nf][2] * ih1 * ip0;
                sims[(row + 8) * LDS_ + col + 1] = acc[mi][nf][3] * ih1 * ip1;
            }
        }
    }
    __syncthreads();

    // ---- per-token router: 20 warps ----
    const float* sims = (const float*)(smem + OFF_SIMS);
    float* out_mask = out;
    float* out_prob = out + (size_t)T * EE;
    float* out_lc   = out + (size_t)2 * T * EE;
    float* out_ls   = out + (size_t)3 * T * EE;

    for (int rr = wid; rr < BM; rr += 20) {
        const float* srow = &sims[rr * LDS_];
        float l0, l1;
        {
            float s0 = srow[2 * lane], s1 = srow[2 * lane + 1];
            float m = fmaxf(s0, s1);
            l0 = 10.0f * (m + logf(expf(s0 - m) + expf(s1 - m)));
            s0 = srow[64 + 2 * lane]; s1 = srow[64 + 2 * lane + 1];
            m = fmaxf(s0, s1);
            l1 = 10.0f * (m + logf(expf(s0 - m) + expf(s1 - m)));
        }

        bool sel0 = false, sel1 = false;
        float mx = -INFINITY;
#pragma unroll
        for (int it = 0; it < TOPK; ++it) {
            float v0 = sel0 ? -INFINITY : l0;
            float v1 = sel1 ? -INFINITY : l1;
            float v; int idx;
            if (v0 >= v1) { v = v0; idx = lane; }
            else          { v = v1; idx = lane + 32; }
            for (int o = 16; o; o >>= 1) {
                float ov = __shfl_down_sync(0xffffffffu, v, o);
                int   oi = __shfl_down_sync(0xffffffffu, idx, o);
                if (ov > v || (ov == v && oi < idx)) { v = ov; idx = oi; }
            }
            int   w  = __shfl_sync(0xffffffffu, idx, 0);
            float wv = __shfl_sync(0xffffffffu, v, 0);
            if (it == 0) mx = wv;
            if (w == lane)           sel0 = true;
            else if (w == lane + 32) sel1 = true;
        }

        float z0 = expf(l0 - mx), z1 = expf(l1 - mx);
        float zs = z0 + z1;
        for (int o = 16; o; o >>= 1) zs += __shfl_xor_sync(0xffffffffu, zs, o);
        float d0 = z0 / zs, d1 = z1 / zs;
        float ms = (sel0 ? d0 : 0.f) + (sel1 ? d1 : 0.f);
        for (int o = 16; o; o >>= 1) ms += __shfl_xor_sync(0xffffffffu, ms, o);
        float inv = 1.0f / (ms + 1e-9f);
        float p0 = sel0 ? d0 * inv : 0.f;
        float p1 = sel1 ? d1 * inv : 0.f;

        size_t bb = (size_t)(t0 + rr) * EE;
        out_mask[bb + lane]      = sel0 ? 1.f : 0.f;
        out_mask[bb + lane + 32] = sel1 ? 1.f : 0.f;
        out_prob[bb + lane]      = p0;
        out_prob[bb + lane + 32] = p1;
        out_lc[bb + lane]        = l0;
        out_lc[bb + lane + 32]   = l1;
        out_ls[bb + lane]        = l0;
        out_ls[bb + lane + 32]   = l1;
    }
}

// ---------------------------------------------------------------------------
extern "C" void kernel_launch(void* const* d_in, const int* in_sizes, int n_in,
                              void* d_out, int out_size) {
    const float* h     = (const float*)d_in[0];
    const float* proto = (const float*)d_in[1];
    float* out = (float*)d_out;
    int T = in_sizes[0] / DK;   // 16384

    prep_kernel<<<640, 256>>>(proto);

    static bool attr_set = false;
    if (!attr_set) {
        cudaFuncSetAttribute(router_mma,
                             cudaFuncAttributeMaxDynamicSharedMemorySize,
                             SMEM_TOTAL);
        attr_set = true;
    }
    router_mma<<<T / BM, NTHREADS, SMEM_TOTAL>>>(h, out, T);
}

// round 11
// speedup vs baseline: 1.2895x; 1.2895x over previous
#include <cuda_runtime.h>
#include <cuda_fp16.h>
#include <math.h>
#include <stdint.h>

// ---------------- problem constants ----------------
#define DK   4096
#define EE   64
#define TOPK 8
#define BM   128
#define BN   128
#define CHUNK 32                 // K floats per stage (two 16-K halves, split over warps)
#define NSTAGE 128
#define NTHREADS 512

// ---------------- smem layout (bytes) ----------------
#define A_STAGE 16384            // [k16(2)][plane(2)][128 rows][32B]
#define B_STAGE 16384            // [k16][pass][n16][lane] uint4
#define OFF_A 0
#define OFF_B (2*A_STAGE)                 // 32768
#define OFF_SIMS (OFF_B + 4*B_STAGE)      // 98304
#define LDS_ 132
#define OFF_HSQ  (OFF_SIMS + 128*LDS_*4)  // 165888
#define OFF_INVH (OFF_HSQ + 512*4)
#define OFF_INVP (OFF_INVH + 128*4)
#define SMEM_TOTAL (OFF_INVP + 128*4)     // 168960

__device__ float g_inv_pnorm[BN];
// B fragments: [kt(128)][k16(2)][pass(2)][n16(8)][lane(32)] -> uint4
__device__ uint4 g_bfrag[NSTAGE * 2 * 2 * 8 * 32];

// ---------------- helpers ----------------
__device__ __forceinline__ uint32_t smem_u32(const void* p) {
    uint32_t a;
    asm("{ .reg .u64 t; cvta.to.shared.u64 t, %1; cvt.u32.u64 %0, t; }" : "=r"(a) : "l"(p));
    return a;
}
__device__ __forceinline__ void ldm4(uint32_t* r, uint32_t addr) {
    asm volatile("ldmatrix.sync.aligned.m8n8.x4.shared.b16 {%0,%1,%2,%3}, [%4];"
        : "=r"(r[0]), "=r"(r[1]), "=r"(r[2]), "=r"(r[3]) : "r"(addr));
}
__device__ __forceinline__ uint4 lds128(uint32_t addr) {
    uint4 v;
    asm volatile("ld.shared.v4.u32 {%0,%1,%2,%3}, [%4];"
        : "=r"(v.x), "=r"(v.y), "=r"(v.z), "=r"(v.w) : "r"(addr));
    return v;
}
__device__ __forceinline__ void mma16816(float* c, const uint32_t* a, uint32_t b0, uint32_t b1) {
    asm volatile("mma.sync.aligned.m16n8k16.row.col.f32.f16.f16.f32 "
        "{%0,%1,%2,%3}, {%4,%5,%6,%7}, {%8,%9}, {%0,%1,%2,%3};"
        : "+f"(c[0]), "+f"(c[1]), "+f"(c[2]), "+f"(c[3])
        : "r"(a[0]), "r"(a[1]), "r"(a[2]), "r"(a[3]), "r"(b0), "r"(b1));
}
__device__ __forceinline__ void split2(float x, float y, uint32_t& uh, uint32_t& ul) {
    asm("cvt.rn.f16x2.f32 %0, %1, %2;" : "=r"(uh) : "f"(y), "f"(x));
    float lx = __half2float(__ushort_as_half((unsigned short)(uh & 0xffffu)));
    float ly = __half2float(__ushort_as_half((unsigned short)(uh >> 16)));
    float rx = x - lx, ry = y - ly;
    asm("cvt.rn.f16x2.f32 %0, %1, %2;" : "=r"(ul) : "f"(ry), "f"(rx));
}
#define CP_ASYNC16(dst, src) \
    asm volatile("cp.async.cg.shared.global [%0], [%1], 16;" :: "r"(dst), "l"(src))
#define CP_COMMIT() asm volatile("cp.async.commit_group;" ::: "memory")
#define CP_WAIT1()  asm volatile("cp.async.wait_group 1;"  ::: "memory")

// ---------------------------------------------------------------------------
// Kernel 1: fused prep — blocks [0,512): B split; blocks [512,640): proto norms
// ---------------------------------------------------------------------------
__global__ void prep_kernel(const float* __restrict__ proto) {
    if (blockIdx.x < 512) {
        int idx  = blockIdx.x * 256 + threadIdx.x;     // 131072 uint4
        int lane = idx & 31;
        int n16  = (idx >> 5) & 7;
        int pass = (idx >> 8) & 1;
        int k16  = (idx >> 9) & 1;
        int kt   = idx >> 10;
        int kt16 = kt * 2 + k16;
        uint32_t w[4];
#pragma unroll
        for (int r = 0; r < 4; r++) {
            int n  = n16 * 16 + ((r & 2) << 2) + (lane >> 2);
            int k0 = kt16 * 16 + (r & 1) * 8 + 2 * (lane & 3);
            float x = proto[(size_t)n * DK + k0];
            float y = proto[(size_t)n * DK + k0 + 1];
            uint32_t uh, ul;
            split2(x, y, uh, ul);
            w[r] = pass ? ul : uh;
        }
        g_bfrag[idx] = make_uint4(w[0], w[1], w[2], w[3]);
    } else {
        int row = blockIdx.x - 512;
        const float4* p = reinterpret_cast<const float4*>(proto + (size_t)row * DK);
        float s = 0.f;
        for (int i = threadIdx.x; i < DK / 4; i += blockDim.x) {
            float4 v = p[i];
            s += v.x * v.x + v.y * v.y + v.z * v.z + v.w * v.w;
        }
        for (int o = 16; o; o >>= 1) s += __shfl_down_sync(0xffffffffu, s, o);
        __shared__ float sm[8];
        if ((threadIdx.x & 31) == 0) sm[threadIdx.x >> 5] = s;
        __syncthreads();
        if (threadIdx.x == 0) {
            float t = 0.f;
            for (int i = 0; i < (int)(blockDim.x >> 5); i++) t += sm[i];
            g_inv_pnorm[row] = 1.0f / (sqrtf(t) + 1e-6f);
        }
    }
}

// ---------------------------------------------------------------------------
// Kernel 2: 3-pass split-fp16 mma GEMM, K-split 64x32 warp tiles (low LDS/MMA)
//   16 warps = 2 K-groups x (2m x 4n); each K-group owns one 16-K half/stage
// ---------------------------------------------------------------------------
extern "C" __global__ void __launch_bounds__(NTHREADS, 1)
router_mma(const float* __restrict__ h, float* __restrict__ out, int T) {
    extern __shared__ char smem[];
    const uint32_t smem_u = smem_u32(smem);
    const int tid  = threadIdx.x;
    const int wid  = tid >> 5;
    const int lane = tid & 31;
    const int t0   = blockIdx.x * BM;

    if (tid < BN) ((float*)(smem + OFF_INVP))[tid] = g_inv_pnorm[tid];

    // A load/convert mapping: row = tid>>2, q = tid&3 -> 8 floats of the 32-chunk
    const int arow_g = tid >> 2;
    const int q      = tid & 3;
    const int k16q   = q >> 1;
    const int halfq  = q & 1;
    const float* ag = h + (size_t)(t0 + arow_g) * DK + q * 8;
    const uint32_t st_hi = OFF_A + (uint32_t)k16q * 8192u + (uint32_t)arow_g * 32u
                         + (uint32_t)((halfq ^ ((arow_g >> 2) & 1)) * 16);
    const uint32_t st_lo = st_hi + 4096u;

    // warp tile: 64 (M) x 32 (N), K-split
    const int ksel    = wid >> 3;                 // 0 or 1: k16 half owned
    const int warp_m  = ((wid >> 2) & 1) * 64;
    const int warp_n4 = (wid & 3) * 2;
    const uint32_t koff  = (uint32_t)ksel * 8192u;
    const uint32_t bwoff = (uint32_t)warp_n4 * 512u + (uint32_t)lane * 16u;

    uint32_t aoff[4];
#pragma unroll
    for (int mi = 0; mi < 4; mi++) {
        int ar = warp_m + mi * 16 + ((lane >> 3) & 1) * 8 + (lane & 7);
        int kh = lane >> 4;
        aoff[mi] = (uint32_t)ar * 32u + (uint32_t)((kh ^ ((ar >> 2) & 1)) * 16);
    }

    float acc[4][4][4];
#pragma unroll
    for (int a = 0; a < 4; a++)
#pragma unroll
        for (int b = 0; b < 4; b++)
#pragma unroll
            for (int c = 0; c < 4; c++) acc[a][b][c] = 0.f;

    float hsum = 0.f;
    float4 av0, av1;

    // ---- prologue: B stages 0..2 cp.async; A chunk 0 convert+store ----
#pragma unroll
    for (int s = 0; s < 3; s++) {
        uint32_t d = smem_u + OFF_B + (uint32_t)s * B_STAGE + (uint32_t)tid * 32u;
        const char* g = (const char*)g_bfrag + (size_t)s * B_STAGE + (size_t)tid * 32;
        CP_ASYNC16(d, g); CP_ASYNC16(d + 16, g + 16);
        CP_COMMIT();
    }
    av0 = ((const float4*)ag)[0]; av1 = ((const float4*)ag)[1];
    {
        uint32_t uh[4], ul[4];
        split2(av0.x, av0.y, uh[0], ul[0]);
        split2(av0.z, av0.w, uh[1], ul[1]);
        split2(av1.x, av1.y, uh[2], ul[2]);
        split2(av1.z, av1.w, uh[3], ul[3]);
        hsum += av0.x*av0.x + av0.y*av0.y + av0.z*av0.z + av0.w*av0.w
              + av1.x*av1.x + av1.y*av1.y + av1.z*av1.z + av1.w*av1.w;
        *(uint4*)(smem + st_hi) = make_uint4(uh[0], uh[1], uh[2], uh[3]);
        *(uint4*)(smem + st_lo) = make_uint4(ul[0], ul[1], ul[2], ul[3]);
    }
    av0 = ((const float4*)(ag + CHUNK))[0];
    av1 = ((const float4*)(ag + CHUNK))[1];
    CP_WAIT1();
    __syncthreads();

    uint4 bh0, bh1, bl0, bl1;
    {   // preload stage-0 B fragments for this warp's k16 half
        uint32_t bb = smem_u + OFF_B + koff;
        bh0 = lds128(bb + bwoff);        bh1 = lds128(bb + bwoff + 512);
        bl0 = lds128(bb + bwoff + 4096); bl1 = lds128(bb + bwoff + 4096 + 512);
    }

    // ---- main loop: one sync per 32-K stage ----
#pragma unroll 1
    for (int kt = 0; kt < NSTAGE; ++kt) {
        const uint32_t abase = smem_u + OFF_A + (uint32_t)(kt & 1) * A_STAGE + koff;

        uint32_t A[4][4];
        ldm4(A[0], abase + aoff[0]);
        ldm4(A[1], abase + aoff[1]);
        ldm4(A[2], abase + aoff[2]);
        ldm4(A[3], abase + aoff[3]);

#pragma unroll
        for (int mi = 0; mi < 4; mi++) {              // pass 1: A_hi x B_hi
            mma16816(acc[mi][0], A[mi], bh0.x, bh0.y);
            mma16816(acc[mi][1], A[mi], bh0.z, bh0.w);
            mma16816(acc[mi][2], A[mi], bh1.x, bh1.y);
            mma16816(acc[mi][3], A[mi], bh1.z, bh1.w);
        }

        // issue B(kt+3) cp.async
        {
            int ks = kt + 3;
            if (ks < NSTAGE) {
                uint32_t d = smem_u + OFF_B + (uint32_t)(ks & 3) * B_STAGE + (uint32_t)tid * 32u;
                const char* g = (const char*)g_bfrag + (size_t)ks * B_STAGE + (size_t)tid * 32;
                CP_ASYNC16(d, g); CP_ASYNC16(d + 16, g + 16);
            }
            CP_COMMIT();
        }

#pragma unroll
        for (int mi = 0; mi < 4; mi++) {              // pass 2: A_hi x B_lo
            mma16816(acc[mi][0], A[mi], bl0.x, bl0.y);
            mma16816(acc[mi][1], A[mi], bl0.z, bl0.w);
            mma16816(acc[mi][2], A[mi], bl1.x, bl1.y);
            mma16816(acc[mi][3], A[mi], bl1.z, bl1.w);
        }

        // convert + store A chunk kt+1 into the other buffer
        if (kt + 1 < NSTAGE) {
            char* stg = smem + ((kt + 1) & 1) * A_STAGE;
            uint32_t uh[4], ul[4];
            split2(av0.x, av0.y, uh[0], ul[0]);
            split2(av0.z, av0.w, uh[1], ul[1]);
            split2(av1.x, av1.y, uh[2], ul[2]);
            split2(av1.z, av1.w, uh[3], ul[3]);
            hsum += av0.x*av0.x + av0.y*av0.y + av0.z*av0.z + av0.w*av0.w
                  + av1.x*av1.x + av1.y*av1.y + av1.z*av1.z + av1.w*av1.w;
            *(uint4*)(stg + st_hi) = make_uint4(uh[0], uh[1], uh[2], uh[3]);
            *(uint4*)(stg + st_lo) = make_uint4(ul[0], ul[1], ul[2], ul[3]);
        }

        // A_lo fragments (reuse registers; Ah dead after pass 2)
        ldm4(A[0], abase + 4096u + aoff[0]);
        ldm4(A[1], abase + 4096u + aoff[1]);
        ldm4(A[2], abase + 4096u + aoff[2]);
        ldm4(A[3], abase + 4096u + aoff[3]);

#pragma unroll
        for (int mi = 0; mi < 4; mi++) {              // pass 3: A_lo x B_hi
            mma16816(acc[mi][0], A[mi], bh0.x, bh0.y);
            mma16816(acc[mi][1], A[mi], bh0.z, bh0.w);
            mma16816(acc[mi][2], A[mi], bh1.x, bh1.y);
            mma16816(acc[mi][3], A[mi], bh1.z, bh1.w);
        }

        // prefetch A chunk kt+2
        {
            int ka = (kt + 2 < NSTAGE) ? kt + 2 : NSTAGE - 1;
            av0 = ((const float4*)(ag + (size_t)ka * CHUNK))[0];
            av1 = ((const float4*)(ag + (size_t)ka * CHUNK))[1];
        }

        CP_WAIT1();
        // preload next-stage B fragments (slot kt+1 complete)
        {
            uint32_t nb = smem_u + OFF_B + (uint32_t)((kt + 1) & 3) * B_STAGE + koff;
            bh0 = lds128(nb + bwoff);        bh1 = lds128(nb + bwoff + 512);
            bl0 = lds128(nb + bwoff + 4096); bl1 = lds128(nb + bwoff + 4096 + 512);
        }
        __syncthreads();
    }

    // ---- token norms ----
    ((float*)(smem + OFF_HSQ))[tid] = hsum;
    __syncthreads();
    if (tid < BM) {
        const float* hsq = (const float*)(smem + OFF_HSQ);
        float s = hsq[4 * tid] + hsq[4 * tid + 1] + hsq[4 * tid + 2] + hsq[4 * tid + 3];
        ((float*)(smem + OFF_INVH))[tid] = 1.0f / (sqrtf(s) + 1e-6f);
    }
    __syncthreads();

    // ---- accumulators -> raw dot sums in smem (two-phase K-group reduce) ----
    {
        float* sims = (float*)(smem + OFF_SIMS);
        const int warp_n = (wid & 3) * 32;
        int lr = lane >> 2, lc = (lane & 3) * 2;
        if (ksel == 0) {
#pragma unroll
            for (int mi = 0; mi < 4; mi++) {
                int row = warp_m + mi * 16 + lr;
#pragma unroll
                for (int nf = 0; nf < 4; nf++) {
                    int col = warp_n + nf * 8 + lc;
                    sims[row * LDS_ + col]           = acc[mi][nf][0];
                    sims[row * LDS_ + col + 1]       = acc[mi][nf][1];
                    sims[(row + 8) * LDS_ + col]     = acc[mi][nf][2];
                    sims[(row + 8) * LDS_ + col + 1] = acc[mi][nf][3];
                }
            }
        }
        __syncthreads();
        if (ksel == 1) {
#pragma unroll
            for (int mi = 0; mi < 4; mi++) {
                int row = warp_m + mi * 16 + lr;
#pragma unroll
                for (int nf = 0; nf < 4; nf++) {
                    int col = warp_n + nf * 8 + lc;
                    sims[row * LDS_ + col]           += acc[mi][nf][0];
                    sims[row * LDS_ + col + 1]       += acc[mi][nf][1];
                    sims[(row + 8) * LDS_ + col]     += acc[mi][nf][2];
                    sims[(row + 8) * LDS_ + col + 1] += acc[mi][nf][3];
                }
            }
        }
    }
    __syncthreads();

    // ---- per-token router: 16 warps, 8 rows each (norms applied inline) ----
    const float* sims = (const float*)(smem + OFF_SIMS);
    const float* invh = (const float*)(smem + OFF_INVH);
    const float* invp = (const float*)(smem + OFF_INVP);
    float* out_mask = out;
    float* out_prob = out + (size_t)T * EE;
    float* out_lc   = out + (size_t)2 * T * EE;
    float* out_ls   = out + (size_t)3 * T * EE;

    for (int rr = wid; rr < BM; rr += 16) {
        const float* srow = &sims[rr * LDS_];
        const float ih = invh[rr];
        float l0, l1;
        {
            float s0 = srow[2 * lane] * ih * invp[2 * lane];
            float s1 = srow[2 * lane + 1] * ih * invp[2 * lane + 1];
            float m = fmaxf(s0, s1);
            l0 = 10.0f * (m + logf(expf(s0 - m) + expf(s1 - m)));
            s0 = srow[64 + 2 * lane] * ih * invp[64 + 2 * lane];
            s1 = srow[64 + 2 * lane + 1] * ih * invp[64 + 2 * lane + 1];
            m = fmaxf(s0, s1);
            l1 = 10.0f * (m + logf(expf(s0 - m) + expf(s1 - m)));
        }

        bool sel0 = false, sel1 = false;
        float mx = -INFINITY;
#pragma unroll
        for (int it = 0; it < TOPK; ++it) {
            float v0 = sel0 ? -INFINITY : l0;
            float v1 = sel1 ? -INFINITY : l1;
            float v; int idx;
            if (v0 >= v1) { v = v0; idx = lane; }
            else          { v = v1; idx = lane + 32; }
            for (int o = 16; o; o >>= 1) {
                float ov = __shfl_down_sync(0xffffffffu, v, o);
                int   oi = __shfl_down_sync(0xffffffffu, idx, o);
                if (ov > v || (ov == v && oi < idx)) { v = ov; idx = oi; }
            }
            int   w  = __shfl_sync(0xffffffffu, idx, 0);
            float wv = __shfl_sync(0xffffffffu, v, 0);
            if (it == 0) mx = wv;
            if (w == lane)           sel0 = true;
            else if (w == lane + 32) sel1 = true;
        }

        float z0 = expf(l0 - mx), z1 = expf(l1 - mx);
        float zs = z0 + z1;
        for (int o = 16; o; o >>= 1) zs += __shfl_xor_sync(0xffffffffu, zs, o);
        float d0 = z0 / zs, d1 = z1 / zs;
        float ms = (sel0 ? d0 : 0.f) + (sel1 ? d1 : 0.f);
        for (int o = 16; o; o >>= 1) ms += __shfl_xor_sync(0xffffffffu, ms, o);
        float inv = 1.0f / (ms + 1e-9f);
        float p0 = sel0 ? d0 * inv : 0.f;
        float p1 = sel1 ? d1 * inv : 0.f;

        size_t bb = (size_t)(t0 + rr) * EE;
        out_mask[bb + lane]      = sel0 ? 1.f : 0.f;
        out_mask[bb + lane + 32] = sel1 ? 1.f : 0.f;
        out_prob[bb + lane]      = p0;
        out_prob[bb + lane + 32] = p1;
        out_lc[bb + lane]        = l0;
        out_lc[bb + lane + 32]   = l1;
        out_ls[bb + lane]        = l0;
        out_ls[bb + lane + 32]   = l1;
    }
}

// ---------------------------------------------------------------------------
extern "C" void kernel_launch(void* const* d_in, const int* in_sizes, int n_in,
                              void* d_out, int out_size) {
    const float* h     = (const float*)d_in[0];
    const float* proto = (const float*)d_in[1];
    float* out = (float*)d_out;
    int T = in_sizes[0] / DK;   // 16384

    prep_kernel<<<640, 256>>>(proto);

    static bool attr_set = false;
    if (!attr_set) {
        cudaFuncSetAttribute(router_mma,
                             cudaFuncAttributeMaxDynamicSharedMemorySize,
                             SMEM_TOTAL);
        attr_set = true;
    }
    router_mma<<<T / BM, NTHREADS, SMEM_TOTAL>>>(h, out, T);
}